// round 2
// baseline (speedup 1.0000x reference)
#include <cuda_runtime.h>
#include <cstdint>

#define B_   8
#define T_   512
#define H_   768
#define L_   12
#define FF_  3072
#define BT_  (B_*T_)
#define EPS_ 1e-5f

// ---------------- scratch (static device globals; no allocation) ----------
__device__ float g_h  [BT_*H_];
__device__ float g_xk [BT_*H_];
__device__ float g_xv [BT_*H_];
__device__ float g_xr [BT_*H_];
__device__ float g_k  [BT_*H_];
__device__ float g_v  [BT_*H_];
__device__ float g_r  [BT_*H_];
__device__ float g_att[BT_*H_];
__device__ float g_kf [BT_*FF_];

// ---------------- block reduction (blockDim == 256) ------------------------
__device__ __forceinline__ float bsum256(float val, float* red) {
    int lane = threadIdx.x & 31;
    int w    = threadIdx.x >> 5;
#pragma unroll
    for (int o = 16; o; o >>= 1) val += __shfl_xor_sync(0xffffffffu, val, o);
    __syncthreads();
    if (lane == 0) red[w] = val;
    __syncthreads();
    float s = 0.f;
#pragma unroll
    for (int i = 0; i < 8; i++) s += red[i];
    return s;
}

// ---------------- plain LayerNorm (one block per row) ----------------------
__global__ void ln_kernel(const float* __restrict__ in,
                          const float* __restrict__ w,
                          const float* __restrict__ b,
                          float* __restrict__ out) {
    __shared__ float red[8];
    size_t base = (size_t)blockIdx.x * H_;
    float c[3];
    float s = 0.f, s2 = 0.f;
#pragma unroll
    for (int i = 0; i < 3; i++) {
        int j = threadIdx.x + i * 256;
        c[i] = in[base + j];
        s += c[i]; s2 += c[i] * c[i];
    }
    s  = bsum256(s,  red);
    s2 = bsum256(s2, red);
    float m  = s / H_;
    float v  = s2 / H_ - m * m;
    float rs = rsqrtf(v + EPS_);
#pragma unroll
    for (int i = 0; i < 3; i++) {
        int j = threadIdx.x + i * 256;
        out[base + j] = (c[i] - m) * rs * w[j] + b[j];
    }
}

// ---------------- LN + token-shift + lerp-mix ------------------------------
__global__ void prep_mix(const float* __restrict__ h,
                         const float* __restrict__ lnw, const float* __restrict__ lnb,
                         const float* __restrict__ mk,  const float* __restrict__ mv,
                         const float* __restrict__ mr,
                         float* __restrict__ xk, float* __restrict__ xv,
                         float* __restrict__ xr) {
    __shared__ float red[8];
    int row = blockIdx.x;
    int t   = row % T_;
    const float* cur = h + (size_t)row * H_;
    float c[3], p[3];
    float sc = 0.f, sc2 = 0.f, sp = 0.f, sp2 = 0.f;
#pragma unroll
    for (int i = 0; i < 3; i++) {
        int j = threadIdx.x + i * 256;
        c[i] = cur[j];
        sc += c[i]; sc2 += c[i] * c[i];
        p[i] = (t > 0) ? cur[j - H_] : 0.f;
        sp += p[i]; sp2 += p[i] * p[i];
    }
    sc  = bsum256(sc,  red);
    sc2 = bsum256(sc2, red);
    sp  = bsum256(sp,  red);
    sp2 = bsum256(sp2, red);
    float mc = sc / H_, vc = sc2 / H_ - mc * mc, rc = rsqrtf(vc + EPS_);
    float mp = sp / H_, vp = sp2 / H_ - mp * mp, rp = rsqrtf(vp + EPS_);
#pragma unroll
    for (int i = 0; i < 3; i++) {
        int j = threadIdx.x + i * 256;
        float w = lnw[j], bb = lnb[j];
        float hn = (c[i] - mc) * rc * w + bb;
        float sh = (t > 0) ? ((p[i] - mp) * rp * w + bb) : 0.f;
        size_t idx = (size_t)row * H_ + j;
        float k_ = mk[j];
        xk[idx] = hn * k_ + sh * (1.f - k_);
        if (xv) {
            float v_ = mv[j];
            xv[idx] = hn * v_ + sh * (1.f - v_);
        }
        float r_ = mr[j];
        xr[idx] = hn * r_ + sh * (1.f - r_);
    }
}

// ---------------- WKV scan: one thread per (b, channel), fuses r-gate ------
__global__ void wkv_kernel(const float* __restrict__ k,
                           const float* __restrict__ v,
                           const float* __restrict__ r,
                           const float* __restrict__ td,
                           const float* __restrict__ tf,
                           float* __restrict__ att) {
    int c = blockIdx.x * blockDim.x + threadIdx.x;
    if (c >= B_ * H_) return;
    int b = c / H_, hh = c % H_;
    float w = -expf(td[hh]);
    float u = tf[hh];
    float num = 0.f, den = 0.f, mx = -1e38f;
    size_t base = (size_t)b * T_ * H_ + hh;
    for (int t = 0; t < T_; t++) {
        size_t idx = base + (size_t)t * H_;
        float kt = k[idx], vt = v[idx];
        float a  = kt + u;
        float mo = fmaxf(mx, a);
        float e1 = expf(mx - mo), e2 = expf(a - mo);
        float out = (e1 * num + e2 * vt) / (e1 * den + e2);
        att[idx] = out * r[idx];
        float ms = fmaxf(mx + w, kt);
        float f1 = expf(mx + w - ms), f2 = expf(kt - ms);
        num = f1 * num + f2 * vt;
        den = f1 * den + f2;
        mx  = ms;
    }
}

// ====================== 3xTF32 tensor-core GEMM ============================
// Block tile 128x128, K-tile 16, 256 threads = 8 warps (2x4), warp tile 64x32.
// Smem holds fp32 in mma-fragment layout; hi/lo split computed in registers.
// EPI: 0 C=acc, 1 C=sigmoid(acc), 2 C+=acc, 3 C+=aux*acc, 4 C=relu(acc)^2

__device__ __forceinline__ void mma_tf32(float c[4], const uint32_t a[4], const uint32_t b[2]) {
    asm volatile(
        "mma.sync.aligned.m16n8k8.row.col.f32.tf32.tf32.f32 "
        "{%0,%1,%2,%3}, {%4,%5,%6,%7}, {%8,%9}, {%0,%1,%2,%3};\n"
        : "+f"(c[0]), "+f"(c[1]), "+f"(c[2]), "+f"(c[3])
        : "r"(a[0]), "r"(a[1]), "r"(a[2]), "r"(a[3]), "r"(b[0]), "r"(b[1]));
}

__device__ __forceinline__ void split1(float x, uint32_t& hi, uint32_t& lo) {
    uint32_t xh = __float_as_uint(x) & 0xffffe000u;
    hi = xh;
    lo = __float_as_uint(x - __uint_as_float(xh));
}

template <int EPI>
__device__ __forceinline__ void epi_apply(float* p, float v, const float* auxp) {
    if (EPI == 0)      *p = v;
    else if (EPI == 1) *p = 1.f / (1.f + expf(-v));
    else if (EPI == 2) *p += v;
    else if (EPI == 3) *p += (*auxp) * v;
    else {             float rr = fmaxf(v, 0.f); *p = rr * rr; }
}

#define KT 16

template <int EPI>
__global__ __launch_bounds__(256)
void tgemm(const float* __restrict__ A, const float* __restrict__ B,
           float* __restrict__ C, const float* __restrict__ aux,
           int M, int N, int K) {
    // [buf][kstep][tile][lane][frag]
    __shared__ float As[2][2][8][32][4];
    __shared__ float Bs[2][2][16][32][2];

    int tid = threadIdx.x;
    int l   = tid & 31;
    int w   = tid >> 5;
    int wm  = w >> 2;          // 0..1
    int wn  = w & 3;           // 0..3
    int bm  = blockIdx.y * 128;
    int bn  = blockIdx.x * 128;

    float acc[4][4][4];
#pragma unroll
    for (int mi = 0; mi < 4; mi++)
#pragma unroll
        for (int ni = 0; ni < 4; ni++)
#pragma unroll
            for (int q = 0; q < 4; q++) acc[mi][ni][q] = 0.f;

    float4 ar[2], br[2];

    // ---- gmem loads for tile at k0 into regs ----
    auto load_regs = [&](int k0) {
#pragma unroll
        for (int q = 0; q < 2; q++) {
            int f = tid + q * 256;               // A: 512 float4 (128 rows x 4)
            int r = f >> 2, c = (f & 3) << 2;
            ar[q] = *(const float4*)&A[(size_t)(bm + r) * K + k0 + c];
        }
#pragma unroll
        for (int q = 0; q < 2; q++) {
            int f = tid + q * 256;               // B: 512 float4 (16 rows x 32)
            int kr = f >> 5, c = (f & 31) << 2;
            br[q] = *(const float4*)&B[(size_t)(k0 + kr) * N + bn + c];
        }
    };

    // ---- scatter regs into fragment-layout smem buffer ----
    auto store_smem = [&](int buf) {
#pragma unroll
        for (int q = 0; q < 2; q++) {
            int f = tid + q * 256;
            int r = f >> 2, c = (f & 3) << 2;
            int ks = c >> 3;
            int j  = ((r >> 3) & 1) + (((c >> 2) & 1) << 1);
            int mt = r >> 4;
            int lb = (r & 7) << 2;
            float v[4] = {ar[q].x, ar[q].y, ar[q].z, ar[q].w};
#pragma unroll
            for (int i = 0; i < 4; i++)
                As[buf][ks][mt][lb + i][j] = v[i];
        }
#pragma unroll
        for (int q = 0; q < 2; q++) {
            int f = tid + q * 256;
            int kr = f >> 5, c = (f & 31) << 2;
            int ks = kr >> 3;
            int j  = (kr >> 2) & 1;
            int nt = c >> 3;
            float v[4] = {br[q].x, br[q].y, br[q].z, br[q].w};
#pragma unroll
            for (int i = 0; i < 4; i++)
                Bs[buf][ks][nt][(((c + i) & 7) << 2) + (kr & 3)][j] = v[i];
        }
    };

    auto compute = [&](int buf) {
#pragma unroll
        for (int s = 0; s < 2; s++) {
            uint32_t ah[4][4], al[4][4], bh[4][2], bl[4][2];
#pragma unroll
            for (int mi = 0; mi < 4; mi++) {
                float4 av = *(const float4*)&As[buf][s][wm * 4 + mi][l][0];
                split1(av.x, ah[mi][0], al[mi][0]);
                split1(av.y, ah[mi][1], al[mi][1]);
                split1(av.z, ah[mi][2], al[mi][2]);
                split1(av.w, ah[mi][3], al[mi][3]);
            }
#pragma unroll
            for (int ni = 0; ni < 4; ni++) {
                float2 bv = *(const float2*)&Bs[buf][s][wn * 4 + ni][l][0];
                split1(bv.x, bh[ni][0], bl[ni][0]);
                split1(bv.y, bh[ni][1], bl[ni][1]);
            }
#pragma unroll
            for (int mi = 0; mi < 4; mi++)
#pragma unroll
                for (int ni = 0; ni < 4; ni++)
                    mma_tf32(acc[mi][ni], ah[mi], bh[ni]);
#pragma unroll
            for (int mi = 0; mi < 4; mi++)
#pragma unroll
                for (int ni = 0; ni < 4; ni++)
                    mma_tf32(acc[mi][ni], al[mi], bh[ni]);
#pragma unroll
            for (int mi = 0; mi < 4; mi++)
#pragma unroll
                for (int ni = 0; ni < 4; ni++)
                    mma_tf32(acc[mi][ni], ah[mi], bl[ni]);
        }
    };

    int ntiles = K / KT;
    load_regs(0);
    store_smem(0);
    __syncthreads();
#pragma unroll 1
    for (int ti = 0; ti < ntiles; ti++) {
        if (ti + 1 < ntiles) load_regs((ti + 1) * KT);
        compute(ti & 1);
        if (ti + 1 < ntiles) store_smem((ti + 1) & 1);
        __syncthreads();
    }

    // ---- epilogue ----
#pragma unroll
    for (int mi = 0; mi < 4; mi++) {
#pragma unroll
        for (int ni = 0; ni < 4; ni++) {
            int r0 = bm + wm * 64 + mi * 16 + (l >> 2);
            int c0 = bn + wn * 32 + ni * 8 + ((l & 3) << 1);
            size_t i0 = (size_t)r0 * N + c0;
            size_t i1 = (size_t)(r0 + 8) * N + c0;
            epi_apply<EPI>(&C[i0],     acc[mi][ni][0], aux ? &aux[i0]     : nullptr);
            epi_apply<EPI>(&C[i0 + 1], acc[mi][ni][1], aux ? &aux[i0 + 1] : nullptr);
            epi_apply<EPI>(&C[i1],     acc[mi][ni][2], aux ? &aux[i1]     : nullptr);
            epi_apply<EPI>(&C[i1 + 1], acc[mi][ni][3], aux ? &aux[i1 + 1] : nullptr);
        }
    }
}

// ---------------- host orchestration ---------------------------------------
extern "C" void kernel_launch(void* const* d_in, const int* in_sizes, int n_in,
                              void* d_out, int out_size) {
    (void)in_sizes; (void)n_in; (void)out_size;
    const float* x     = (const float*)d_in[0];
    const float* prew  = (const float*)d_in[1];
    const float* preb  = (const float*)d_in[2];
    const float* ln1w  = (const float*)d_in[3];
    const float* ln1b  = (const float*)d_in[4];
    const float* ln2w  = (const float*)d_in[5];
    const float* ln2b  = (const float*)d_in[6];
    const float* td    = (const float*)d_in[7];
    const float* tf    = (const float*)d_in[8];
    const float* amk   = (const float*)d_in[9];
    const float* amv   = (const float*)d_in[10];
    const float* amr   = (const float*)d_in[11];
    const float* Wk    = (const float*)d_in[12];
    const float* Wv    = (const float*)d_in[13];
    const float* Wr    = (const float*)d_in[14];
    const float* Wo    = (const float*)d_in[15];
    const float* fmk   = (const float*)d_in[16];
    const float* fmr   = (const float*)d_in[17];
    const float* Fk    = (const float*)d_in[18];
    const float* Fv    = (const float*)d_in[19];
    const float* Fr    = (const float*)d_in[20];
    const float* lnow  = (const float*)d_in[21];
    const float* lnob  = (const float*)d_in[22];
    const float* headw = (const float*)d_in[23];

    float *h, *xk, *xv, *xr, *k, *v, *r, *att, *kf;
    cudaGetSymbolAddress((void**)&h,   g_h);
    cudaGetSymbolAddress((void**)&xk,  g_xk);
    cudaGetSymbolAddress((void**)&xv,  g_xv);
    cudaGetSymbolAddress((void**)&xr,  g_xr);
    cudaGetSymbolAddress((void**)&k,   g_k);
    cudaGetSymbolAddress((void**)&v,   g_v);
    cudaGetSymbolAddress((void**)&r,   g_r);
    cudaGetSymbolAddress((void**)&att, g_att);
    cudaGetSymbolAddress((void**)&kf,  g_kf);

    dim3 blk(256);
    dim3 gH(H_ / 128,  BT_ / 128);   // (6, 32)
    dim3 gF(FF_ / 128, BT_ / 128);   // (24, 32)

    ln_kernel<<<BT_, blk>>>(x, prew, preb, h);

    for (int i = 0; i < L_; i++) {
        size_t oH  = (size_t)i * H_;
        size_t oHH = (size_t)i * H_ * H_;
        size_t oHF = (size_t)i * H_ * FF_;

        // --- time mixing ---
        prep_mix<<<BT_, blk>>>(h, ln1w + oH, ln1b + oH,
                               amk + oH, amv + oH, amr + oH, xk, xv, xr);
        tgemm<0><<<gH, blk>>>(xk, Wk + oHH, k,  nullptr, BT_, H_, H_);
        tgemm<0><<<gH, blk>>>(xv, Wv + oHH, v,  nullptr, BT_, H_, H_);
        tgemm<1><<<gH, blk>>>(xr, Wr + oHH, r,  nullptr, BT_, H_, H_);
        wkv_kernel<<<(B_ * H_ + 255) / 256, blk>>>(k, v, r, td + oH, tf + oH, att);
        tgemm<2><<<gH, blk>>>(att, Wo + oHH, h, nullptr, BT_, H_, H_);

        // --- channel mixing ---
        prep_mix<<<BT_, blk>>>(h, ln2w + oH, ln2b + oH,
                               fmk + oH, nullptr, fmr + oH, xk, nullptr, xr);
        tgemm<4><<<gF, blk>>>(xk, Fk + oHF, kf, nullptr, BT_, FF_, H_);
        tgemm<1><<<gH, blk>>>(xr, Fr + oHH, r,  nullptr, BT_, H_, H_);
        tgemm<3><<<gH, blk>>>(kf, Fv + oHF, h,  r,       BT_, H_, FF_);
    }

    ln_kernel<<<BT_, blk>>>(h, lnow, lnob, h);
    tgemm<0><<<gH, blk>>>(h, headw, (float*)d_out, nullptr, BT_, H_, H_);
}

// round 3
// speedup vs baseline: 2.7465x; 2.7465x over previous
#include <cuda_runtime.h>
#include <cuda_bf16.h>
#include <cstdint>

#define B_   8
#define T_   512
#define H_   768
#define L_   12
#define FF_  3072
#define BT_  (B_*T_)
#define EPS_ 1e-5f

#define H2_  (H_*H_)
#define HFF_ (H_*FF_)
#define WL_  (5*H2_ + 2*HFF_)          // per-layer split-weight block
#define WTOT_ (L_*WL_ + H2_)           // + head

// offsets within a layer block (element units)
#define OWK_ 0
#define OWV_ (1*H2_)
#define OWR_ (2*H2_)
#define OWO_ (3*H2_)
#define OFR_ (4*H2_)
#define OFK_ (5*H2_)
#define OFV_ (5*H2_ + HFF_)

// ---------------- scratch (static device globals; no allocation) ----------
__device__ float g_h[BT_*H_];
__device__ float g_k[BT_*H_];
__device__ float g_v[BT_*H_];
__device__ float g_r[BT_*H_];

__device__ __align__(16) __nv_bfloat16 g_wh [WTOT_];
__device__ __align__(16) __nv_bfloat16 g_wl [WTOT_];
__device__ __align__(16) __nv_bfloat16 g_xkh[BT_*H_], g_xkl[BT_*H_];
__device__ __align__(16) __nv_bfloat16 g_xvh[BT_*H_], g_xvl[BT_*H_];
__device__ __align__(16) __nv_bfloat16 g_xrh[BT_*H_], g_xrl[BT_*H_];
__device__ __align__(16) __nv_bfloat16 g_ath[BT_*H_], g_atl[BT_*H_];
__device__ __align__(16) __nv_bfloat16 g_kfh[BT_*FF_], g_kfl[BT_*FF_];

// ---------------- helpers ---------------------------------------------------
__device__ __forceinline__ void fsplit(float x, __nv_bfloat16& h, __nv_bfloat16& l) {
    h = __float2bfloat16_rn(x);
    l = __float2bfloat16_rn(x - __bfloat162float(h));
}

__device__ __forceinline__ float bsum256(float val, float* red) {
    int lane = threadIdx.x & 31;
    int w    = threadIdx.x >> 5;
#pragma unroll
    for (int o = 16; o; o >>= 1) val += __shfl_xor_sync(0xffffffffu, val, o);
    __syncthreads();
    if (lane == 0) red[w] = val;
    __syncthreads();
    float s = 0.f;
#pragma unroll
    for (int i = 0; i < 8; i++) s += red[i];
    return s;
}

// ---------------- weight transpose + split: [K][N] fp32 -> [N][K] bf16 hi/lo
__global__ void transT(const float* __restrict__ in,
                       __nv_bfloat16* __restrict__ oh,
                       __nv_bfloat16* __restrict__ ol, int Kd, int Nd) {
    __shared__ float t[32][33];
    int n0 = blockIdx.x * 32, k0 = blockIdx.y * 32;
    int tx = threadIdx.x, ty = threadIdx.y;   // 32 x 8
#pragma unroll
    for (int i = 0; i < 32; i += 8)
        t[ty + i][tx] = in[(size_t)(k0 + ty + i) * Nd + n0 + tx];
    __syncthreads();
#pragma unroll
    for (int i = 0; i < 32; i += 8) {
        float x = t[tx][ty + i];
        __nv_bfloat16 h, l; fsplit(x, h, l);
        size_t o = (size_t)(n0 + ty + i) * Kd + k0 + tx;
        oh[o] = h; ol[o] = l;
    }
}

// ---------------- pre-LN (fp32 out, block 0 only) --------------------------
__global__ void ln_kernel(const float* __restrict__ in,
                          const float* __restrict__ w,
                          const float* __restrict__ b,
                          float* __restrict__ out) {
    __shared__ float red[8];
    size_t base = (size_t)blockIdx.x * H_;
    float c[3];
    float s = 0.f, s2 = 0.f;
#pragma unroll
    for (int i = 0; i < 3; i++) {
        int j = threadIdx.x + i * 256;
        c[i] = in[base + j];
        s += c[i]; s2 += c[i] * c[i];
    }
    s  = bsum256(s,  red);
    s2 = bsum256(s2, red);
    float m = s / H_, v = s2 / H_ - m * m, rs = rsqrtf(v + EPS_);
#pragma unroll
    for (int i = 0; i < 3; i++) {
        int j = threadIdx.x + i * 256;
        out[base + j] = (c[i] - m) * rs * w[j] + b[j];
    }
}

// ---------------- final LN, split-output -----------------------------------
__global__ void ln_split(const float* __restrict__ in,
                         const float* __restrict__ w,
                         const float* __restrict__ b,
                         __nv_bfloat16* __restrict__ oh,
                         __nv_bfloat16* __restrict__ ol) {
    __shared__ float red[8];
    size_t base = (size_t)blockIdx.x * H_;
    float c[3];
    float s = 0.f, s2 = 0.f;
#pragma unroll
    for (int i = 0; i < 3; i++) {
        int j = threadIdx.x + i * 256;
        c[i] = in[base + j];
        s += c[i]; s2 += c[i] * c[i];
    }
    s  = bsum256(s,  red);
    s2 = bsum256(s2, red);
    float m = s / H_, v = s2 / H_ - m * m, rs = rsqrtf(v + EPS_);
#pragma unroll
    for (int i = 0; i < 3; i++) {
        int j = threadIdx.x + i * 256;
        float x = (c[i] - m) * rs * w[j] + b[j];
        __nv_bfloat16 h, l; fsplit(x, h, l);
        oh[base + j] = h; ol[base + j] = l;
    }
}

// ---------------- LN + token-shift + lerp-mix, split-output ----------------
__global__ void prep_mix(const float* __restrict__ hbuf,
                         const float* __restrict__ lnw, const float* __restrict__ lnb,
                         const float* __restrict__ mk,  const float* __restrict__ mv,
                         const float* __restrict__ mr,
                         __nv_bfloat16* __restrict__ xkh, __nv_bfloat16* __restrict__ xkl,
                         __nv_bfloat16* __restrict__ xvh, __nv_bfloat16* __restrict__ xvl,
                         __nv_bfloat16* __restrict__ xrh, __nv_bfloat16* __restrict__ xrl) {
    __shared__ float red[8];
    int row = blockIdx.x;
    int t   = row % T_;
    const float* cur = hbuf + (size_t)row * H_;
    float c[3], p[3];
    float sc = 0.f, sc2 = 0.f, sp = 0.f, sp2 = 0.f;
#pragma unroll
    for (int i = 0; i < 3; i++) {
        int j = threadIdx.x + i * 256;
        c[i] = cur[j];
        sc += c[i]; sc2 += c[i] * c[i];
        p[i] = (t > 0) ? cur[j - H_] : 0.f;
        sp += p[i]; sp2 += p[i] * p[i];
    }
    sc  = bsum256(sc,  red);
    sc2 = bsum256(sc2, red);
    sp  = bsum256(sp,  red);
    sp2 = bsum256(sp2, red);
    float mc = sc / H_, vc = sc2 / H_ - mc * mc, rc = rsqrtf(vc + EPS_);
    float mp = sp / H_, vp = sp2 / H_ - mp * mp, rp = rsqrtf(vp + EPS_);
#pragma unroll
    for (int i = 0; i < 3; i++) {
        int j = threadIdx.x + i * 256;
        float w = lnw[j], bb = lnb[j];
        float hn = (c[i] - mc) * rc * w + bb;
        float sh = (t > 0) ? ((p[i] - mp) * rp * w + bb) : 0.f;
        size_t idx = (size_t)row * H_ + j;
        __nv_bfloat16 hh, ll;
        float k_ = mk[j];
        fsplit(hn * k_ + sh * (1.f - k_), hh, ll);
        xkh[idx] = hh; xkl[idx] = ll;
        if (xvh) {
            float v_ = mv[j];
            fsplit(hn * v_ + sh * (1.f - v_), hh, ll);
            xvh[idx] = hh; xvl[idx] = ll;
        }
        float r_ = mr[j];
        fsplit(hn * r_ + sh * (1.f - r_), hh, ll);
        xrh[idx] = hh; xrl[idx] = ll;
    }
}

// ---------------- WKV scan, fuses r-gate + split output --------------------
__global__ void wkv_kernel(const float* __restrict__ k,
                           const float* __restrict__ v,
                           const float* __restrict__ r,
                           const float* __restrict__ td,
                           const float* __restrict__ tf,
                           __nv_bfloat16* __restrict__ ah,
                           __nv_bfloat16* __restrict__ al) {
    int c = blockIdx.x * blockDim.x + threadIdx.x;
    if (c >= B_ * H_) return;
    int b = c / H_, hh = c % H_;
    float w = -expf(td[hh]);
    float u = tf[hh];
    float num = 0.f, den = 0.f, mx = -1e38f;
    size_t base = (size_t)b * T_ * H_ + hh;
    for (int t = 0; t < T_; t++) {
        size_t idx = base + (size_t)t * H_;
        float kt = k[idx], vt = v[idx];
        float a  = kt + u;
        float mo = fmaxf(mx, a);
        float e1 = expf(mx - mo), e2 = expf(a - mo);
        float out = ((e1 * num + e2 * vt) / (e1 * den + e2)) * r[idx];
        __nv_bfloat16 oh, ol; fsplit(out, oh, ol);
        ah[idx] = oh; al[idx] = ol;
        float ms = fmaxf(mx + w, kt);
        float f1 = expf(mx + w - ms), f2 = expf(kt - ms);
        num = f1 * num + f2 * vt;
        den = f1 * den + f2;
        mx  = ms;
    }
}

// ====================== bf16 3-term tensor-core GEMM =======================
// A [M][K] bf16 hi/lo (k-major), B [N][K] bf16 hi/lo (k-major, pre-transposed)
// C[M][N] fp32 (or bf16 hi/lo split for EPI 4).
// Block 128x128, K-tile 32, 8 warps (2x4), warp tile 64x32, 4-stage cp.async.

#define STAGES 4
#define STAGE_BYTES 32768
#define TILE_BYTES  8192
#define GEMM_SMEM   (STAGES*STAGE_BYTES)

__device__ __forceinline__ uint32_t goff(int row, int kg) {
    int p = row >> 1;
    int c = (kg ^ (p & 3)) | ((row & 1) << 2);
    return (uint32_t)((p * 8 + c) * 16);
}

__device__ __forceinline__ void cpa16(uint32_t dst, const void* src) {
    asm volatile("cp.async.cg.shared.global [%0], [%1], 16;\n" :: "r"(dst), "l"(src));
}

__device__ __forceinline__ void ldsm4(uint32_t r[4], uint32_t a) {
    asm volatile("ldmatrix.sync.aligned.m8n8.x4.shared.b16 {%0,%1,%2,%3}, [%4];\n"
                 : "=r"(r[0]), "=r"(r[1]), "=r"(r[2]), "=r"(r[3]) : "r"(a));
}

__device__ __forceinline__ void mma16816(float c[4], const uint32_t a[4],
                                         uint32_t b0, uint32_t b1) {
    asm volatile(
        "mma.sync.aligned.m16n8k16.row.col.f32.bf16.bf16.f32 "
        "{%0,%1,%2,%3}, {%4,%5,%6,%7}, {%8,%9}, {%0,%1,%2,%3};\n"
        : "+f"(c[0]), "+f"(c[1]), "+f"(c[2]), "+f"(c[3])
        : "r"(a[0]), "r"(a[1]), "r"(a[2]), "r"(a[3]), "r"(b0), "r"(b1));
}

template <int EPI>
__device__ __forceinline__ void epi1(float* C, __nv_bfloat16* Oh, __nv_bfloat16* Ol,
                                     const float* aux, size_t idx, float v) {
    if (EPI == 0)      C[idx] = v;
    else if (EPI == 1) C[idx] = 1.f / (1.f + expf(-v));
    else if (EPI == 2) C[idx] += v;
    else if (EPI == 3) C[idx] += aux[idx] * v;
    else {
        float rr = fmaxf(v, 0.f); float q = rr * rr;
        __nv_bfloat16 h, l; fsplit(q, h, l);
        Oh[idx] = h; Ol[idx] = l;
    }
}

template <int EPI>
__global__ __launch_bounds__(256)
void tgemm(const __nv_bfloat16* __restrict__ Ah, const __nv_bfloat16* __restrict__ Al,
           const __nv_bfloat16* __restrict__ Bh, const __nv_bfloat16* __restrict__ Bl,
           float* __restrict__ C, const float* __restrict__ aux,
           __nv_bfloat16* __restrict__ Oh, __nv_bfloat16* __restrict__ Ol,
           int M, int N, int K) {
    extern __shared__ __align__(16) uint8_t sm8[];
    uint32_t sb = (uint32_t)__cvta_generic_to_shared(sm8);

    int tid = threadIdx.x;
    int l   = tid & 31;
    int w   = tid >> 5;
    int wm  = w >> 2;           // 0..1
    int wn  = w & 3;            // 0..3
    int bm  = blockIdx.y * 128;
    int bn  = blockIdx.x * 128;

    float acc[4][4][4];
#pragma unroll
    for (int mi = 0; mi < 4; mi++)
#pragma unroll
        for (int ni = 0; ni < 4; ni++)
#pragma unroll
            for (int q = 0; q < 4; q++) acc[mi][ni][q] = 0.f;

    auto load_stage = [&](int s, int k0) {
        uint32_t st = sb + s * STAGE_BYTES;
#pragma unroll
        for (int q = 0; q < 2; q++) {
            int gid = tid + q * 256;
            int row = gid >> 2, kg = gid & 3;
            uint32_t off = goff(row, kg);
            size_t ga = (size_t)(bm + row) * K + k0 + kg * 8;
            size_t gb = (size_t)(bn + row) * K + k0 + kg * 8;
            cpa16(st + off,                 Ah + ga);
            cpa16(st + TILE_BYTES + off,    Al + ga);
            cpa16(st + 2*TILE_BYTES + off,  Bh + gb);
            cpa16(st + 3*TILE_BYTES + off,  Bl + gb);
        }
        asm volatile("cp.async.commit_group;\n" ::);
    };

    int nt = K / 32;
    load_stage(0, 0);
    load_stage(1, 32);
    load_stage(2, 64);

#pragma unroll 1
    for (int i = 0; i < nt; i++) {
        int rem = nt - 1 - i;
        if (rem >= 2)      asm volatile("cp.async.wait_group 2;\n" ::);
        else if (rem == 1) asm volatile("cp.async.wait_group 1;\n" ::);
        else               asm volatile("cp.async.wait_group 0;\n" ::);
        __syncthreads();

        uint32_t st = sb + (i & 3) * STAGE_BYTES;
        int sub = l >> 3;
#pragma unroll
        for (int ks = 0; ks < 2; ks++) {
            uint32_t ah[4][4], al[4][4], bh[2][4], bl[2][4];
#pragma unroll
            for (int mi = 0; mi < 4; mi++) {
                int row = wm * 64 + mi * 16 + (l & 7) + ((sub & 1) << 3);
                int kg  = ks * 2 + (sub >> 1);
                uint32_t a = st + goff(row, kg);
                ldsm4(ah[mi], a);
                ldsm4(al[mi], a + TILE_BYTES);
            }
#pragma unroll
            for (int g = 0; g < 2; g++) {
                int row = wn * 32 + g * 16 + (l & 7) + ((sub >> 1) << 3);
                int kg  = ks * 2 + (sub & 1);
                uint32_t b = st + 2*TILE_BYTES + goff(row, kg);
                ldsm4(bh[g], b);
                ldsm4(bl[g], b + TILE_BYTES);
            }
#pragma unroll
            for (int mi = 0; mi < 4; mi++)
#pragma unroll
                for (int ni = 0; ni < 4; ni++) {
                    int g = ni >> 1, o = (ni & 1) * 2;
                    mma16816(acc[mi][ni], al[mi], bh[g][o], bh[g][o + 1]);
                }
#pragma unroll
            for (int mi = 0; mi < 4; mi++)
#pragma unroll
                for (int ni = 0; ni < 4; ni++) {
                    int g = ni >> 1, o = (ni & 1) * 2;
                    mma16816(acc[mi][ni], ah[mi], bl[g][o], bl[g][o + 1]);
                }
#pragma unroll
            for (int mi = 0; mi < 4; mi++)
#pragma unroll
                for (int ni = 0; ni < 4; ni++) {
                    int g = ni >> 1, o = (ni & 1) * 2;
                    mma16816(acc[mi][ni], ah[mi], bh[g][o], bh[g][o + 1]);
                }
        }
        if (i + 3 < nt) load_stage((i + 3) & 3, (i + 3) * 32);
    }

    // ---- epilogue ----
#pragma unroll
    for (int mi = 0; mi < 4; mi++) {
#pragma unroll
        for (int ni = 0; ni < 4; ni++) {
            int r0 = bm + wm * 64 + mi * 16 + (l >> 2);
            int c0 = bn + wn * 32 + ni * 8 + (l & 3) * 2;
            size_t i0 = (size_t)r0 * N + c0;
            size_t i1 = (size_t)(r0 + 8) * N + c0;
            epi1<EPI>(C, Oh, Ol, aux, i0,     acc[mi][ni][0]);
            epi1<EPI>(C, Oh, Ol, aux, i0 + 1, acc[mi][ni][1]);
            epi1<EPI>(C, Oh, Ol, aux, i1,     acc[mi][ni][2]);
            epi1<EPI>(C, Oh, Ol, aux, i1 + 1, acc[mi][ni][3]);
        }
    }
}

// ---------------- host orchestration ---------------------------------------
extern "C" void kernel_launch(void* const* d_in, const int* in_sizes, int n_in,
                              void* d_out, int out_size) {
    (void)in_sizes; (void)n_in; (void)out_size;
    const float* x     = (const float*)d_in[0];
    const float* prew  = (const float*)d_in[1];
    const float* preb  = (const float*)d_in[2];
    const float* ln1w  = (const float*)d_in[3];
    const float* ln1b  = (const float*)d_in[4];
    const float* ln2w  = (const float*)d_in[5];
    const float* ln2b  = (const float*)d_in[6];
    const float* td    = (const float*)d_in[7];
    const float* tf    = (const float*)d_in[8];
    const float* amk   = (const float*)d_in[9];
    const float* amv   = (const float*)d_in[10];
    const float* amr   = (const float*)d_in[11];
    const float* Wk    = (const float*)d_in[12];
    const float* Wv    = (const float*)d_in[13];
    const float* Wr    = (const float*)d_in[14];
    const float* Wo    = (const float*)d_in[15];
    const float* fmk   = (const float*)d_in[16];
    const float* fmr   = (const float*)d_in[17];
    const float* Fk    = (const float*)d_in[18];
    const float* Fv    = (const float*)d_in[19];
    const float* Fr    = (const float*)d_in[20];
    const float* lnow  = (const float*)d_in[21];
    const float* lnob  = (const float*)d_in[22];
    const float* headw = (const float*)d_in[23];

    float *h, *k, *v, *r;
    __nv_bfloat16 *wh, *wl, *xkh, *xkl, *xvh, *xvl, *xrh, *xrl, *ath, *atl, *kfh, *kfl;
    cudaGetSymbolAddress((void**)&h,   g_h);
    cudaGetSymbolAddress((void**)&k,   g_k);
    cudaGetSymbolAddress((void**)&v,   g_v);
    cudaGetSymbolAddress((void**)&r,   g_r);
    cudaGetSymbolAddress((void**)&wh,  g_wh);
    cudaGetSymbolAddress((void**)&wl,  g_wl);
    cudaGetSymbolAddress((void**)&xkh, g_xkh);
    cudaGetSymbolAddress((void**)&xkl, g_xkl);
    cudaGetSymbolAddress((void**)&xvh, g_xvh);
    cudaGetSymbolAddress((void**)&xvl, g_xvl);
    cudaGetSymbolAddress((void**)&xrh, g_xrh);
    cudaGetSymbolAddress((void**)&xrl, g_xrl);
    cudaGetSymbolAddress((void**)&ath, g_ath);
    cudaGetSymbolAddress((void**)&atl, g_atl);
    cudaGetSymbolAddress((void**)&kfh, g_kfh);
    cudaGetSymbolAddress((void**)&kfl, g_kfl);

    cudaFuncSetAttribute(tgemm<0>, cudaFuncAttributeMaxDynamicSharedMemorySize, GEMM_SMEM);
    cudaFuncSetAttribute(tgemm<1>, cudaFuncAttributeMaxDynamicSharedMemorySize, GEMM_SMEM);
    cudaFuncSetAttribute(tgemm<2>, cudaFuncAttributeMaxDynamicSharedMemorySize, GEMM_SMEM);
    cudaFuncSetAttribute(tgemm<3>, cudaFuncAttributeMaxDynamicSharedMemorySize, GEMM_SMEM);
    cudaFuncSetAttribute(tgemm<4>, cudaFuncAttributeMaxDynamicSharedMemorySize, GEMM_SMEM);

    dim3 blk(256);
    dim3 tb(32, 8);
    dim3 gHH(H_ / 32, H_ / 32);     // transT grids
    dim3 gHF(FF_ / 32, H_ / 32);    // Fk: K=H, N=FF
    dim3 gFH(H_ / 32, FF_ / 32);    // Fv: K=FF, N=H
    dim3 gH(H_ / 128,  BT_ / 128);  // GEMM grids
    dim3 gF(FF_ / 128, BT_ / 128);

    // ---- weight transpose + split (independent of activations) ----
    for (int i = 0; i < L_; i++) {
        size_t wb = (size_t)i * WL_;
        transT<<<gHH, tb>>>(Wk + (size_t)i * H2_,  wh + wb + OWK_, wl + wb + OWK_, H_, H_);
        transT<<<gHH, tb>>>(Wv + (size_t)i * H2_,  wh + wb + OWV_, wl + wb + OWV_, H_, H_);
        transT<<<gHH, tb>>>(Wr + (size_t)i * H2_,  wh + wb + OWR_, wl + wb + OWR_, H_, H_);
        transT<<<gHH, tb>>>(Wo + (size_t)i * H2_,  wh + wb + OWO_, wl + wb + OWO_, H_, H_);
        transT<<<gHH, tb>>>(Fr + (size_t)i * H2_,  wh + wb + OFR_, wl + wb + OFR_, H_, H_);
        transT<<<gHF, tb>>>(Fk + (size_t)i * HFF_, wh + wb + OFK_, wl + wb + OFK_, H_, FF_);
        transT<<<gFH, tb>>>(Fv + (size_t)i * HFF_, wh + wb + OFV_, wl + wb + OFV_, FF_, H_);
    }
    size_t hb = (size_t)L_ * WL_;
    transT<<<gHH, tb>>>(headw, wh + hb, wl + hb, H_, H_);

    // ---- block 0 pre-LN ----
    ln_kernel<<<BT_, blk>>>(x, prew, preb, h);

    for (int i = 0; i < L_; i++) {
        size_t oH = (size_t)i * H_;
        size_t wb = (size_t)i * WL_;

        // --- time mixing ---
        prep_mix<<<BT_, blk>>>(h, ln1w + oH, ln1b + oH, amk + oH, amv + oH, amr + oH,
                               xkh, xkl, xvh, xvl, xrh, xrl);
        tgemm<0><<<gH, blk, GEMM_SMEM>>>(xkh, xkl, wh + wb + OWK_, wl + wb + OWK_,
                                         k, nullptr, nullptr, nullptr, BT_, H_, H_);
        tgemm<0><<<gH, blk, GEMM_SMEM>>>(xvh, xvl, wh + wb + OWV_, wl + wb + OWV_,
                                         v, nullptr, nullptr, nullptr, BT_, H_, H_);
        tgemm<1><<<gH, blk, GEMM_SMEM>>>(xrh, xrl, wh + wb + OWR_, wl + wb + OWR_,
                                         r, nullptr, nullptr, nullptr, BT_, H_, H_);
        wkv_kernel<<<(B_ * H_ + 255) / 256, blk>>>(k, v, r, td + oH, tf + oH, ath, atl);
        tgemm<2><<<gH, blk, GEMM_SMEM>>>(ath, atl, wh + wb + OWO_, wl + wb + OWO_,
                                         h, nullptr, nullptr, nullptr, BT_, H_, H_);

        // --- channel mixing ---
        prep_mix<<<BT_, blk>>>(h, ln2w + oH, ln2b + oH, fmk + oH, nullptr, fmr + oH,
                               xkh, xkl, nullptr, nullptr, xrh, xrl);
        tgemm<4><<<gF, blk, GEMM_SMEM>>>(xkh, xkl, wh + wb + OFK_, wl + wb + OFK_,
                                         nullptr, nullptr, kfh, kfl, BT_, FF_, H_);
        tgemm<1><<<gH, blk, GEMM_SMEM>>>(xrh, xrl, wh + wb + OFR_, wl + wb + OFR_,
                                         r, nullptr, nullptr, nullptr, BT_, H_, H_);
        tgemm<3><<<gH, blk, GEMM_SMEM>>>(kfh, kfl, wh + wb + OFV_, wl + wb + OFV_,
                                         h, r, nullptr, nullptr, BT_, H_, FF_);
    }

    ln_split<<<BT_, blk>>>(h, lnow, lnob, xkh, xkl);
    tgemm<0><<<gH, blk, GEMM_SMEM>>>(xkh, xkl, wh + hb, wl + hb,
                                     (float*)d_out, nullptr, nullptr, nullptr, BT_, H_, H_);
}

// round 4
// speedup vs baseline: 2.7534x; 1.0025x over previous
#include <cuda_runtime.h>
#include <cuda_bf16.h>
#include <cstdint>

#define B_   8
#define T_   512
#define H_   768
#define L_   12
#define FF_  3072
#define BT_  (B_*T_)
#define EPS_ 1e-5f

#define H2_  (H_*H_)
#define HFF_ (H_*FF_)
#define WL_  (5*H2_ + 2*HFF_)          // per-layer split-weight block
#define WTOT_ (L_*WL_ + H2_)           // + head

// offsets within a layer block (element units)
#define OWK_ 0
#define OWV_ (1*H2_)
#define OWR_ (2*H2_)
#define OWO_ (3*H2_)
#define OFR_ (4*H2_)
#define OFK_ (5*H2_)
#define OFV_ (5*H2_ + HFF_)

// ---------------- scratch (static device globals; no allocation) ----------
__device__ float g_h[BT_*H_];
__device__ float g_k[BT_*H_];
__device__ float g_v[BT_*H_];
__device__ float g_r[BT_*H_];

__device__ __align__(16) __nv_bfloat16 g_wh [WTOT_];
__device__ __align__(16) __nv_bfloat16 g_wl [WTOT_];
__device__ __align__(16) __nv_bfloat16 g_xkh[BT_*H_], g_xkl[BT_*H_];
__device__ __align__(16) __nv_bfloat16 g_xvh[BT_*H_], g_xvl[BT_*H_];
__device__ __align__(16) __nv_bfloat16 g_xrh[BT_*H_], g_xrl[BT_*H_];
__device__ __align__(16) __nv_bfloat16 g_ath[BT_*H_], g_atl[BT_*H_];
__device__ __align__(16) __nv_bfloat16 g_kfh[BT_*FF_], g_kfl[BT_*FF_];

// ---------------- helpers ---------------------------------------------------
__device__ __forceinline__ void fsplit(float x, __nv_bfloat16& h, __nv_bfloat16& l) {
    h = __float2bfloat16_rn(x);
    l = __float2bfloat16_rn(x - __bfloat162float(h));
}

__device__ __forceinline__ float bsum256(float val, float* red) {
    int lane = threadIdx.x & 31;
    int w    = threadIdx.x >> 5;
#pragma unroll
    for (int o = 16; o; o >>= 1) val += __shfl_xor_sync(0xffffffffu, val, o);
    __syncthreads();
    if (lane == 0) red[w] = val;
    __syncthreads();
    float s = 0.f;
#pragma unroll
    for (int i = 0; i < 8; i++) s += red[i];
    return s;
}

// ---------------- weight transpose + split: [K][N] fp32 -> [N][K] bf16 hi/lo
__global__ void transT(const float* __restrict__ in,
                       __nv_bfloat16* __restrict__ oh,
                       __nv_bfloat16* __restrict__ ol, int Kd, int Nd) {
    __shared__ float t[32][33];
    int n0 = blockIdx.x * 32, k0 = blockIdx.y * 32;
    int tx = threadIdx.x, ty = threadIdx.y;   // 32 x 8
#pragma unroll
    for (int i = 0; i < 32; i += 8)
        t[ty + i][tx] = in[(size_t)(k0 + ty + i) * Nd + n0 + tx];
    __syncthreads();
#pragma unroll
    for (int i = 0; i < 32; i += 8) {
        float x = t[tx][ty + i];
        __nv_bfloat16 h, l; fsplit(x, h, l);
        size_t o = (size_t)(n0 + ty + i) * Kd + k0 + tx;
        oh[o] = h; ol[o] = l;
    }
}

// ---------------- pre-LN (fp32 out, block 0 only) --------------------------
__global__ void ln_kernel(const float* __restrict__ in,
                          const float* __restrict__ w,
                          const float* __restrict__ b,
                          float* __restrict__ out) {
    __shared__ float red[8];
    size_t base = (size_t)blockIdx.x * H_;
    float c[3];
    float s = 0.f, s2 = 0.f;
#pragma unroll
    for (int i = 0; i < 3; i++) {
        int j = threadIdx.x + i * 256;
        c[i] = in[base + j];
        s += c[i]; s2 += c[i] * c[i];
    }
    s  = bsum256(s,  red);
    s2 = bsum256(s2, red);
    float m = s / H_, v = s2 / H_ - m * m, rs = rsqrtf(v + EPS_);
#pragma unroll
    for (int i = 0; i < 3; i++) {
        int j = threadIdx.x + i * 256;
        out[base + j] = (c[i] - m) * rs * w[j] + b[j];
    }
}

// ---------------- final LN, split-output -----------------------------------
__global__ void ln_split(const float* __restrict__ in,
                         const float* __restrict__ w,
                         const float* __restrict__ b,
                         __nv_bfloat16* __restrict__ oh,
                         __nv_bfloat16* __restrict__ ol) {
    __shared__ float red[8];
    size_t base = (size_t)blockIdx.x * H_;
    float c[3];
    float s = 0.f, s2 = 0.f;
#pragma unroll
    for (int i = 0; i < 3; i++) {
        int j = threadIdx.x + i * 256;
        c[i] = in[base + j];
        s += c[i]; s2 += c[i] * c[i];
    }
    s  = bsum256(s,  red);
    s2 = bsum256(s2, red);
    float m = s / H_, v = s2 / H_ - m * m, rs = rsqrtf(v + EPS_);
#pragma unroll
    for (int i = 0; i < 3; i++) {
        int j = threadIdx.x + i * 256;
        float x = (c[i] - m) * rs * w[j] + b[j];
        __nv_bfloat16 h, l; fsplit(x, h, l);
        oh[base + j] = h; ol[base + j] = l;
    }
}

// ---------------- LN + token-shift + lerp-mix, split-output ----------------
__global__ void prep_mix(const float* __restrict__ hbuf,
                         const float* __restrict__ lnw, const float* __restrict__ lnb,
                         const float* __restrict__ mk,  const float* __restrict__ mv,
                         const float* __restrict__ mr,
                         __nv_bfloat16* __restrict__ xkh, __nv_bfloat16* __restrict__ xkl,
                         __nv_bfloat16* __restrict__ xvh, __nv_bfloat16* __restrict__ xvl,
                         __nv_bfloat16* __restrict__ xrh, __nv_bfloat16* __restrict__ xrl) {
    __shared__ float red[8];
    int row = blockIdx.x;
    int t   = row % T_;
    const float* cur = hbuf + (size_t)row * H_;
    float c[3], p[3];
    float sc = 0.f, sc2 = 0.f, sp = 0.f, sp2 = 0.f;
#pragma unroll
    for (int i = 0; i < 3; i++) {
        int j = threadIdx.x + i * 256;
        c[i] = cur[j];
        sc += c[i]; sc2 += c[i] * c[i];
        p[i] = (t > 0) ? cur[j - H_] : 0.f;
        sp += p[i]; sp2 += p[i] * p[i];
    }
    sc  = bsum256(sc,  red);
    sc2 = bsum256(sc2, red);
    sp  = bsum256(sp,  red);
    sp2 = bsum256(sp2, red);
    float mc = sc / H_, vc = sc2 / H_ - mc * mc, rc = rsqrtf(vc + EPS_);
    float mp = sp / H_, vp = sp2 / H_ - mp * mp, rp = rsqrtf(vp + EPS_);
#pragma unroll
    for (int i = 0; i < 3; i++) {
        int j = threadIdx.x + i * 256;
        float w = lnw[j], bb = lnb[j];
        float hn = (c[i] - mc) * rc * w + bb;
        float sh = (t > 0) ? ((p[i] - mp) * rp * w + bb) : 0.f;
        size_t idx = (size_t)row * H_ + j;
        __nv_bfloat16 hh, ll;
        float k_ = mk[j];
        fsplit(hn * k_ + sh * (1.f - k_), hh, ll);
        xkh[idx] = hh; xkl[idx] = ll;
        if (xvh) {
            float v_ = mv[j];
            fsplit(hn * v_ + sh * (1.f - v_), hh, ll);
            xvh[idx] = hh; xvl[idx] = ll;
        }
        float r_ = mr[j];
        fsplit(hn * r_ + sh * (1.f - r_), hh, ll);
        xrh[idx] = hh; xrl[idx] = ll;
    }
}

// ---------------- WKV scan, fuses r-gate + split output --------------------
__global__ void wkv_kernel(const float* __restrict__ k,
                           const float* __restrict__ v,
                           const float* __restrict__ r,
                           const float* __restrict__ td,
                           const float* __restrict__ tf,
                           __nv_bfloat16* __restrict__ ah,
                           __nv_bfloat16* __restrict__ al) {
    int c = blockIdx.x * blockDim.x + threadIdx.x;
    if (c >= B_ * H_) return;
    int b = c / H_, hh = c % H_;
    float w = -expf(td[hh]);
    float u = tf[hh];
    float num = 0.f, den = 0.f, mx = -1e38f;
    size_t base = (size_t)b * T_ * H_ + hh;
    for (int t = 0; t < T_; t++) {
        size_t idx = base + (size_t)t * H_;
        float kt = k[idx], vt = v[idx];
        float a  = kt + u;
        float mo = fmaxf(mx, a);
        float e1 = expf(mx - mo), e2 = expf(a - mo);
        float out = ((e1 * num + e2 * vt) / (e1 * den + e2)) * r[idx];
        __nv_bfloat16 oh, ol; fsplit(out, oh, ol);
        ah[idx] = oh; al[idx] = ol;
        float ms = fmaxf(mx + w, kt);
        float f1 = expf(mx + w - ms), f2 = expf(kt - ms);
        num = f1 * num + f2 * vt;
        den = f1 * den + f2;
        mx  = ms;
    }
}

// ====================== bf16 3-term tensor-core GEMM =======================
// A [M][K] bf16 hi/lo (k-major), B [N][K] bf16 hi/lo (k-major, pre-transposed)
// C[M][N] fp32 (or bf16 hi/lo split for EPI 4).
// Block 128x128, K-tile 32, 8 warps (2x4), warp tile 64x32, 4-stage cp.async.

#define STAGES 4
#define STAGE_BYTES 32768
#define TILE_BYTES  8192
#define GEMM_SMEM   (STAGES*STAGE_BYTES)

__device__ __forceinline__ uint32_t goff(int row, int kg) {
    int p = row >> 1;
    int c = (kg ^ (p & 3)) | ((row & 1) << 2);
    return (uint32_t)((p * 8 + c) * 16);
}

__device__ __forceinline__ void cpa16(uint32_t dst, const void* src) {
    asm volatile("cp.async.cg.shared.global [%0], [%1], 16;\n" :: "r"(dst), "l"(src));
}

__device__ __forceinline__ void ldsm4(uint32_t r[4], uint32_t a) {
    asm volatile("ldmatrix.sync.aligned.m8n8.x4.shared.b16 {%0,%1,%2,%3}, [%4];\n"
                 : "=r"(r[0]), "=r"(r[1]), "=r"(r[2]), "=r"(r[3]) : "r"(a));
}

__device__ __forceinline__ void mma16816(float c[4], const uint32_t a[4],
                                         uint32_t b0, uint32_t b1) {
    asm volatile(
        "mma.sync.aligned.m16n8k16.row.col.f32.bf16.bf16.f32 "
        "{%0,%1,%2,%3}, {%4,%5,%6,%7}, {%8,%9}, {%0,%1,%2,%3};\n"
        : "+f"(c[0]), "+f"(c[1]), "+f"(c[2]), "+f"(c[3])
        : "r"(a[0]), "r"(a[1]), "r"(a[2]), "r"(a[3]), "r"(b0), "r"(b1));
}

template <int EPI>
__device__ __forceinline__ void epi1(float* C, __nv_bfloat16* Oh, __nv_bfloat16* Ol,
                                     const float* aux, size_t idx, float v) {
    if (EPI == 0)      C[idx] = v;
    else if (EPI == 1) C[idx] = 1.f / (1.f + expf(-v));
    else if (EPI == 2) C[idx] += v;
    else if (EPI == 3) C[idx] += aux[idx] * v;
    else {
        float rr = fmaxf(v, 0.f); float q = rr * rr;
        __nv_bfloat16 h, l; fsplit(q, h, l);
        Oh[idx] = h; Ol[idx] = l;
    }
}

template <int EPI>
__global__ __launch_bounds__(256)
void tgemm(const __nv_bfloat16* __restrict__ Ah, const __nv_bfloat16* __restrict__ Al,
           const __nv_bfloat16* __restrict__ Bh, const __nv_bfloat16* __restrict__ Bl,
           float* __restrict__ C, const float* __restrict__ aux,
           __nv_bfloat16* __restrict__ Oh, __nv_bfloat16* __restrict__ Ol,
           int M, int N, int K) {
    extern __shared__ __align__(16) uint8_t sm8[];
    uint32_t sb = (uint32_t)__cvta_generic_to_shared(sm8);

    int tid = threadIdx.x;
    int l   = tid & 31;
    int w   = tid >> 5;
    int wm  = w >> 2;           // 0..1
    int wn  = w & 3;            // 0..3
    int bm  = blockIdx.y * 128;
    int bn  = blockIdx.x * 128;

    float acc[4][4][4];
#pragma unroll
    for (int mi = 0; mi < 4; mi++)
#pragma unroll
        for (int ni = 0; ni < 4; ni++)
#pragma unroll
            for (int q = 0; q < 4; q++) acc[mi][ni][q] = 0.f;

    auto load_stage = [&](int s, int k0) {
        uint32_t st = sb + s * STAGE_BYTES;
#pragma unroll
        for (int q = 0; q < 2; q++) {
            int gid = tid + q * 256;
            int row = gid >> 2, kg = gid & 3;
            uint32_t off = goff(row, kg);
            size_t ga = (size_t)(bm + row) * K + k0 + kg * 8;
            size_t gb = (size_t)(bn + row) * K + k0 + kg * 8;
            cpa16(st + off,                 Ah + ga);
            cpa16(st + TILE_BYTES + off,    Al + ga);
            cpa16(st + 2*TILE_BYTES + off,  Bh + gb);
            cpa16(st + 3*TILE_BYTES + off,  Bl + gb);
        }
        asm volatile("cp.async.commit_group;\n" ::);
    };

    int nt = K / 32;
    load_stage(0, 0);
    load_stage(1, 32);
    load_stage(2, 64);

#pragma unroll 1
    for (int i = 0; i < nt; i++) {
        int rem = nt - 1 - i;
        if (rem >= 2)      asm volatile("cp.async.wait_group 2;\n" ::);
        else if (rem == 1) asm volatile("cp.async.wait_group 1;\n" ::);
        else               asm volatile("cp.async.wait_group 0;\n" ::);
        __syncthreads();

        uint32_t st = sb + (i & 3) * STAGE_BYTES;
        int sub = l >> 3;
#pragma unroll
        for (int ks = 0; ks < 2; ks++) {
            uint32_t ah[4][4], al[4][4], bh[2][4], bl[2][4];
#pragma unroll
            for (int mi = 0; mi < 4; mi++) {
                int row = wm * 64 + mi * 16 + (l & 7) + ((sub & 1) << 3);
                int kg  = ks * 2 + (sub >> 1);
                uint32_t a = st + goff(row, kg);
                ldsm4(ah[mi], a);
                ldsm4(al[mi], a + TILE_BYTES);
            }
#pragma unroll
            for (int g = 0; g < 2; g++) {
                int row = wn * 32 + g * 16 + (l & 7) + ((sub >> 1) << 3);
                int kg  = ks * 2 + (sub & 1);
                uint32_t b = st + 2*TILE_BYTES + goff(row, kg);
                ldsm4(bh[g], b);
                ldsm4(bl[g], b + TILE_BYTES);
            }
#pragma unroll
            for (int mi = 0; mi < 4; mi++)
#pragma unroll
                for (int ni = 0; ni < 4; ni++) {
                    int g = ni >> 1, o = (ni & 1) * 2;
                    mma16816(acc[mi][ni], al[mi], bh[g][o], bh[g][o + 1]);
                }
#pragma unroll
            for (int mi = 0; mi < 4; mi++)
#pragma unroll
                for (int ni = 0; ni < 4; ni++) {
                    int g = ni >> 1, o = (ni & 1) * 2;
                    mma16816(acc[mi][ni], ah[mi], bl[g][o], bl[g][o + 1]);
                }
#pragma unroll
            for (int mi = 0; mi < 4; mi++)
#pragma unroll
                for (int ni = 0; ni < 4; ni++) {
                    int g = ni >> 1, o = (ni & 1) * 2;
                    mma16816(acc[mi][ni], ah[mi], bh[g][o], bh[g][o + 1]);
                }
        }
        if (i + 3 < nt) load_stage((i + 3) & 3, (i + 3) * 32);
    }

    // ---- epilogue ----
#pragma unroll
    for (int mi = 0; mi < 4; mi++) {
#pragma unroll
        for (int ni = 0; ni < 4; ni++) {
            int r0 = bm + wm * 64 + mi * 16 + (l >> 2);
            int c0 = bn + wn * 32 + ni * 8 + (l & 3) * 2;
            size_t i0 = (size_t)r0 * N + c0;
            size_t i1 = (size_t)(r0 + 8) * N + c0;
            epi1<EPI>(C, Oh, Ol, aux, i0,     acc[mi][ni][0]);
            epi1<EPI>(C, Oh, Ol, aux, i0 + 1, acc[mi][ni][1]);
            epi1<EPI>(C, Oh, Ol, aux, i1,     acc[mi][ni][2]);
            epi1<EPI>(C, Oh, Ol, aux, i1 + 1, acc[mi][ni][3]);
        }
    }
}

// ---------------- host orchestration ---------------------------------------
extern "C" void kernel_launch(void* const* d_in, const int* in_sizes, int n_in,
                              void* d_out, int out_size) {
    (void)in_sizes; (void)n_in; (void)out_size;
    const float* x     = (const float*)d_in[0];
    const float* prew  = (const float*)d_in[1];
    const float* preb  = (const float*)d_in[2];
    const float* ln1w  = (const float*)d_in[3];
    const float* ln1b  = (const float*)d_in[4];
    const float* ln2w  = (const float*)d_in[5];
    const float* ln2b  = (const float*)d_in[6];
    const float* td    = (const float*)d_in[7];
    const float* tf    = (const float*)d_in[8];
    const float* amk   = (const float*)d_in[9];
    const float* amv   = (const float*)d_in[10];
    const float* amr   = (const float*)d_in[11];
    const float* Wk    = (const float*)d_in[12];
    const float* Wv    = (const float*)d_in[13];
    const float* Wr    = (const float*)d_in[14];
    const float* Wo    = (const float*)d_in[15];
    const float* fmk   = (const float*)d_in[16];
    const float* fmr   = (const float*)d_in[17];
    const float* Fk    = (const float*)d_in[18];
    const float* Fv    = (const float*)d_in[19];
    const float* Fr    = (const float*)d_in[20];
    const float* lnow  = (const float*)d_in[21];
    const float* lnob  = (const float*)d_in[22];
    const float* headw = (const float*)d_in[23];

    float *h, *k, *v, *r;
    __nv_bfloat16 *wh, *wl, *xkh, *xkl, *xvh, *xvl, *xrh, *xrl, *ath, *atl, *kfh, *kfl;
    cudaGetSymbolAddress((void**)&h,   g_h);
    cudaGetSymbolAddress((void**)&k,   g_k);
    cudaGetSymbolAddress((void**)&v,   g_v);
    cudaGetSymbolAddress((void**)&r,   g_r);
    cudaGetSymbolAddress((void**)&wh,  g_wh);
    cudaGetSymbolAddress((void**)&wl,  g_wl);
    cudaGetSymbolAddress((void**)&xkh, g_xkh);
    cudaGetSymbolAddress((void**)&xkl, g_xkl);
    cudaGetSymbolAddress((void**)&xvh, g_xvh);
    cudaGetSymbolAddress((void**)&xvl, g_xvl);
    cudaGetSymbolAddress((void**)&xrh, g_xrh);
    cudaGetSymbolAddress((void**)&xrl, g_xrl);
    cudaGetSymbolAddress((void**)&ath, g_ath);
    cudaGetSymbolAddress((void**)&atl, g_atl);
    cudaGetSymbolAddress((void**)&kfh, g_kfh);
    cudaGetSymbolAddress((void**)&kfl, g_kfl);

    cudaFuncSetAttribute(tgemm<0>, cudaFuncAttributeMaxDynamicSharedMemorySize, GEMM_SMEM);
    cudaFuncSetAttribute(tgemm<1>, cudaFuncAttributeMaxDynamicSharedMemorySize, GEMM_SMEM);
    cudaFuncSetAttribute(tgemm<2>, cudaFuncAttributeMaxDynamicSharedMemorySize, GEMM_SMEM);
    cudaFuncSetAttribute(tgemm<3>, cudaFuncAttributeMaxDynamicSharedMemorySize, GEMM_SMEM);
    cudaFuncSetAttribute(tgemm<4>, cudaFuncAttributeMaxDynamicSharedMemorySize, GEMM_SMEM);

    dim3 blk(256);
    dim3 tb(32, 8);
    dim3 gHH(H_ / 32, H_ / 32);     // transT grids
    dim3 gHF(FF_ / 32, H_ / 32);    // Fk: K=H, N=FF
    dim3 gFH(H_ / 32, FF_ / 32);    // Fv: K=FF, N=H
    dim3 gH(H_ / 128,  BT_ / 128);  // GEMM grids
    dim3 gF(FF_ / 128, BT_ / 128);

    // ---- weight transpose + split (independent of activations) ----
    for (int i = 0; i < L_; i++) {
        size_t wb = (size_t)i * WL_;
        transT<<<gHH, tb>>>(Wk + (size_t)i * H2_,  wh + wb + OWK_, wl + wb + OWK_, H_, H_);
        transT<<<gHH, tb>>>(Wv + (size_t)i * H2_,  wh + wb + OWV_, wl + wb + OWV_, H_, H_);
        transT<<<gHH, tb>>>(Wr + (size_t)i * H2_,  wh + wb + OWR_, wl + wb + OWR_, H_, H_);
        transT<<<gHH, tb>>>(Wo + (size_t)i * H2_,  wh + wb + OWO_, wl + wb + OWO_, H_, H_);
        transT<<<gHH, tb>>>(Fr + (size_t)i * H2_,  wh + wb + OFR_, wl + wb + OFR_, H_, H_);
        transT<<<gHF, tb>>>(Fk + (size_t)i * HFF_, wh + wb + OFK_, wl + wb + OFK_, H_, FF_);
        transT<<<gFH, tb>>>(Fv + (size_t)i * HFF_, wh + wb + OFV_, wl + wb + OFV_, FF_, H_);
    }
    size_t hb = (size_t)L_ * WL_;
    transT<<<gHH, tb>>>(headw, wh + hb, wl + hb, H_, H_);

    // ---- block 0 pre-LN ----
    ln_kernel<<<BT_, blk>>>(x, prew, preb, h);

    for (int i = 0; i < L_; i++) {
        size_t oH = (size_t)i * H_;
        size_t wb = (size_t)i * WL_;

        // --- time mixing ---
        prep_mix<<<BT_, blk>>>(h, ln1w + oH, ln1b + oH, amk + oH, amv + oH, amr + oH,
                               xkh, xkl, xvh, xvl, xrh, xrl);
        tgemm<0><<<gH, blk, GEMM_SMEM>>>(xkh, xkl, wh + wb + OWK_, wl + wb + OWK_,
                                         k, nullptr, nullptr, nullptr, BT_, H_, H_);
        tgemm<0><<<gH, blk, GEMM_SMEM>>>(xvh, xvl, wh + wb + OWV_, wl + wb + OWV_,
                                         v, nullptr, nullptr, nullptr, BT_, H_, H_);
        tgemm<1><<<gH, blk, GEMM_SMEM>>>(xrh, xrl, wh + wb + OWR_, wl + wb + OWR_,
                                         r, nullptr, nullptr, nullptr, BT_, H_, H_);
        wkv_kernel<<<(B_ * H_ + 255) / 256, blk>>>(k, v, r, td + oH, tf + oH, ath, atl);
        tgemm<2><<<gH, blk, GEMM_SMEM>>>(ath, atl, wh + wb + OWO_, wl + wb + OWO_,
                                         h, nullptr, nullptr, nullptr, BT_, H_, H_);

        // --- channel mixing ---
        prep_mix<<<BT_, blk>>>(h, ln2w + oH, ln2b + oH, fmk + oH, nullptr, fmr + oH,
                               xkh, xkl, nullptr, nullptr, xrh, xrl);
        tgemm<4><<<gF, blk, GEMM_SMEM>>>(xkh, xkl, wh + wb + OFK_, wl + wb + OFK_,
                                         nullptr, nullptr, kfh, kfl, BT_, FF_, H_);
        tgemm<1><<<gH, blk, GEMM_SMEM>>>(xrh, xrl, wh + wb + OFR_, wl + wb + OFR_,
                                         r, nullptr, nullptr, nullptr, BT_, H_, H_);
        tgemm<3><<<gH, blk, GEMM_SMEM>>>(kfh, kfl, wh + wb + OFV_, wl + wb + OFV_,
                                         h, r, nullptr, nullptr, BT_, H_, FF_);
    }

    ln_split<<<BT_, blk>>>(h, lnow, lnob, xkh, xkl);
    tgemm<0><<<gH, blk, GEMM_SMEM>>>(xkh, xkl, wh + hb, wl + hb,
                                     (float*)d_out, nullptr, nullptr, nullptr, BT_, H_, H_);
}

// round 5
// speedup vs baseline: 2.7536x; 1.0000x over previous
#include <cuda_runtime.h>
#include <cuda_bf16.h>
#include <cstdint>

#define B_   8
#define T_   512
#define H_   768
#define L_   12
#define FF_  3072
#define BT_  (B_*T_)
#define EPS_ 1e-5f

#define H2_  (H_*H_)
#define HFF_ (H_*FF_)
#define WL_  (5*H2_ + 2*HFF_)          // per-layer split-weight block
#define WTOT_ (L_*WL_ + H2_)           // + head

// offsets within a layer block (element units)
#define OWK_ 0
#define OWV_ (1*H2_)
#define OWR_ (2*H2_)
#define OWO_ (3*H2_)
#define OFR_ (4*H2_)
#define OFK_ (5*H2_)
#define OFV_ (5*H2_ + HFF_)

// ---------------- scratch (static device globals; no allocation) ----------
__device__ float g_h[BT_*H_];
__device__ float g_k[BT_*H_];
__device__ float g_v[BT_*H_];
__device__ float g_r[BT_*H_];

__device__ __align__(16) __nv_bfloat16 g_wh [WTOT_];
__device__ __align__(16) __nv_bfloat16 g_wl [WTOT_];
__device__ __align__(16) __nv_bfloat16 g_xkh[BT_*H_], g_xkl[BT_*H_];
__device__ __align__(16) __nv_bfloat16 g_xvh[BT_*H_], g_xvl[BT_*H_];
__device__ __align__(16) __nv_bfloat16 g_xrh[BT_*H_], g_xrl[BT_*H_];
__device__ __align__(16) __nv_bfloat16 g_ath[BT_*H_], g_atl[BT_*H_];
__device__ __align__(16) __nv_bfloat16 g_kfh[BT_*FF_], g_kfl[BT_*FF_];

// ---------------- helpers ---------------------------------------------------
__device__ __forceinline__ void fsplit(float x, __nv_bfloat16& h, __nv_bfloat16& l) {
    h = __float2bfloat16_rn(x);
    l = __float2bfloat16_rn(x - __bfloat162float(h));
}

__device__ __forceinline__ float bsum256(float val, float* red) {
    int lane = threadIdx.x & 31;
    int w    = threadIdx.x >> 5;
#pragma unroll
    for (int o = 16; o; o >>= 1) val += __shfl_xor_sync(0xffffffffu, val, o);
    __syncthreads();
    if (lane == 0) red[w] = val;
    __syncthreads();
    float s = 0.f;
#pragma unroll
    for (int i = 0; i < 8; i++) s += red[i];
    return s;
}

// ---------------- weight transpose + split: [K][N] fp32 -> [N][K] bf16 hi/lo
__global__ void transT(const float* __restrict__ in,
                       __nv_bfloat16* __restrict__ oh,
                       __nv_bfloat16* __restrict__ ol, int Kd, int Nd) {
    __shared__ float t[32][33];
    int n0 = blockIdx.x * 32, k0 = blockIdx.y * 32;
    int tx = threadIdx.x, ty = threadIdx.y;   // 32 x 8
#pragma unroll
    for (int i = 0; i < 32; i += 8)
        t[ty + i][tx] = in[(size_t)(k0 + ty + i) * Nd + n0 + tx];
    __syncthreads();
#pragma unroll
    for (int i = 0; i < 32; i += 8) {
        float x = t[tx][ty + i];
        __nv_bfloat16 h, l; fsplit(x, h, l);
        size_t o = (size_t)(n0 + ty + i) * Kd + k0 + tx;
        oh[o] = h; ol[o] = l;
    }
}

// ---------------- pre-LN (fp32 out, block 0 only) --------------------------
__global__ void ln_kernel(const float* __restrict__ in,
                          const float* __restrict__ w,
                          const float* __restrict__ b,
                          float* __restrict__ out) {
    __shared__ float red[8];
    size_t base = (size_t)blockIdx.x * H_;
    float c[3];
    float s = 0.f, s2 = 0.f;
#pragma unroll
    for (int i = 0; i < 3; i++) {
        int j = threadIdx.x + i * 256;
        c[i] = in[base + j];
        s += c[i]; s2 += c[i] * c[i];
    }
    s  = bsum256(s,  red);
    s2 = bsum256(s2, red);
    float m = s / H_, v = s2 / H_ - m * m, rs = rsqrtf(v + EPS_);
#pragma unroll
    for (int i = 0; i < 3; i++) {
        int j = threadIdx.x + i * 256;
        out[base + j] = (c[i] - m) * rs * w[j] + b[j];
    }
}

// ---------------- final LN, split-output -----------------------------------
__global__ void ln_split(const float* __restrict__ in,
                         const float* __restrict__ w,
                         const float* __restrict__ b,
                         __nv_bfloat16* __restrict__ oh,
                         __nv_bfloat16* __restrict__ ol) {
    __shared__ float red[8];
    size_t base = (size_t)blockIdx.x * H_;
    float c[3];
    float s = 0.f, s2 = 0.f;
#pragma unroll
    for (int i = 0; i < 3; i++) {
        int j = threadIdx.x + i * 256;
        c[i] = in[base + j];
        s += c[i]; s2 += c[i] * c[i];
    }
    s  = bsum256(s,  red);
    s2 = bsum256(s2, red);
    float m = s / H_, v = s2 / H_ - m * m, rs = rsqrtf(v + EPS_);
#pragma unroll
    for (int i = 0; i < 3; i++) {
        int j = threadIdx.x + i * 256;
        float x = (c[i] - m) * rs * w[j] + b[j];
        __nv_bfloat16 h, l; fsplit(x, h, l);
        oh[base + j] = h; ol[base + j] = l;
    }
}

// ---------------- LN + token-shift + lerp-mix, split-output ----------------
__global__ void prep_mix(const float* __restrict__ hbuf,
                         const float* __restrict__ lnw, const float* __restrict__ lnb,
                         const float* __restrict__ mk,  const float* __restrict__ mv,
                         const float* __restrict__ mr,
                         __nv_bfloat16* __restrict__ xkh, __nv_bfloat16* __restrict__ xkl,
                         __nv_bfloat16* __restrict__ xvh, __nv_bfloat16* __restrict__ xvl,
                         __nv_bfloat16* __restrict__ xrh, __nv_bfloat16* __restrict__ xrl) {
    __shared__ float red[8];
    int row = blockIdx.x;
    int t   = row % T_;
    const float* cur = hbuf + (size_t)row * H_;
    float c[3], p[3];
    float sc = 0.f, sc2 = 0.f, sp = 0.f, sp2 = 0.f;
#pragma unroll
    for (int i = 0; i < 3; i++) {
        int j = threadIdx.x + i * 256;
        c[i] = cur[j];
        sc += c[i]; sc2 += c[i] * c[i];
        p[i] = (t > 0) ? cur[j - H_] : 0.f;
        sp += p[i]; sp2 += p[i] * p[i];
    }
    sc  = bsum256(sc,  red);
    sc2 = bsum256(sc2, red);
    sp  = bsum256(sp,  red);
    sp2 = bsum256(sp2, red);
    float mc = sc / H_, vc = sc2 / H_ - mc * mc, rc = rsqrtf(vc + EPS_);
    float mp = sp / H_, vp = sp2 / H_ - mp * mp, rp = rsqrtf(vp + EPS_);
#pragma unroll
    for (int i = 0; i < 3; i++) {
        int j = threadIdx.x + i * 256;
        float w = lnw[j], bb = lnb[j];
        float hn = (c[i] - mc) * rc * w + bb;
        float sh = (t > 0) ? ((p[i] - mp) * rp * w + bb) : 0.f;
        size_t idx = (size_t)row * H_ + j;
        __nv_bfloat16 hh, ll;
        float k_ = mk[j];
        fsplit(hn * k_ + sh * (1.f - k_), hh, ll);
        xkh[idx] = hh; xkl[idx] = ll;
        if (xvh) {
            float v_ = mv[j];
            fsplit(hn * v_ + sh * (1.f - v_), hh, ll);
            xvh[idx] = hh; xvl[idx] = ll;
        }
        float r_ = mr[j];
        fsplit(hn * r_ + sh * (1.f - r_), hh, ll);
        xrh[idx] = hh; xrl[idx] = ll;
    }
}

// ---------------- WKV scan, fuses r-gate + split output --------------------
__global__ void wkv_kernel(const float* __restrict__ k,
                           const float* __restrict__ v,
                           const float* __restrict__ r,
                           const float* __restrict__ td,
                           const float* __restrict__ tf,
                           __nv_bfloat16* __restrict__ ah,
                           __nv_bfloat16* __restrict__ al) {
    int c = blockIdx.x * blockDim.x + threadIdx.x;
    if (c >= B_ * H_) return;
    int b = c / H_, hh = c % H_;
    float w = -expf(td[hh]);
    float u = tf[hh];
    float num = 0.f, den = 0.f, mx = -1e38f;
    size_t base = (size_t)b * T_ * H_ + hh;
    for (int t = 0; t < T_; t++) {
        size_t idx = base + (size_t)t * H_;
        float kt = k[idx], vt = v[idx];
        float a  = kt + u;
        float mo = fmaxf(mx, a);
        float e1 = expf(mx - mo), e2 = expf(a - mo);
        float out = ((e1 * num + e2 * vt) / (e1 * den + e2)) * r[idx];
        __nv_bfloat16 oh, ol; fsplit(out, oh, ol);
        ah[idx] = oh; al[idx] = ol;
        float ms = fmaxf(mx + w, kt);
        float f1 = expf(mx + w - ms), f2 = expf(kt - ms);
        num = f1 * num + f2 * vt;
        den = f1 * den + f2;
        mx  = ms;
    }
}

// ====================== bf16 3-term tensor-core GEMM =======================
// A [M][K] bf16 hi/lo (k-major), B [N][K] bf16 hi/lo (k-major, pre-transposed)
// C[M][N] fp32 (or bf16 hi/lo split for EPI 4).
// Block 128x128, K-tile 32, 8 warps (2x4), warp tile 64x32, 4-stage cp.async.

#define STAGES 4
#define STAGE_BYTES 32768
#define TILE_BYTES  8192
#define GEMM_SMEM   (STAGES*STAGE_BYTES)

__device__ __forceinline__ uint32_t goff(int row, int kg) {
    int p = row >> 1;
    int c = (kg ^ (p & 3)) | ((row & 1) << 2);
    return (uint32_t)((p * 8 + c) * 16);
}

__device__ __forceinline__ void cpa16(uint32_t dst, const void* src) {
    asm volatile("cp.async.cg.shared.global [%0], [%1], 16;\n" :: "r"(dst), "l"(src));
}

__device__ __forceinline__ void ldsm4(uint32_t r[4], uint32_t a) {
    asm volatile("ldmatrix.sync.aligned.m8n8.x4.shared.b16 {%0,%1,%2,%3}, [%4];\n"
                 : "=r"(r[0]), "=r"(r[1]), "=r"(r[2]), "=r"(r[3]) : "r"(a));
}

__device__ __forceinline__ void mma16816(float c[4], const uint32_t a[4],
                                         uint32_t b0, uint32_t b1) {
    asm volatile(
        "mma.sync.aligned.m16n8k16.row.col.f32.bf16.bf16.f32 "
        "{%0,%1,%2,%3}, {%4,%5,%6,%7}, {%8,%9}, {%0,%1,%2,%3};\n"
        : "+f"(c[0]), "+f"(c[1]), "+f"(c[2]), "+f"(c[3])
        : "r"(a[0]), "r"(a[1]), "r"(a[2]), "r"(a[3]), "r"(b0), "r"(b1));
}

template <int EPI>
__device__ __forceinline__ void epi1(float* C, __nv_bfloat16* Oh, __nv_bfloat16* Ol,
                                     const float* aux, size_t idx, float v) {
    if (EPI == 0)      C[idx] = v;
    else if (EPI == 1) C[idx] = 1.f / (1.f + expf(-v));
    else if (EPI == 2) C[idx] += v;
    else if (EPI == 3) C[idx] += aux[idx] * v;
    else {
        float rr = fmaxf(v, 0.f); float q = rr * rr;
        __nv_bfloat16 h, l; fsplit(q, h, l);
        Oh[idx] = h; Ol[idx] = l;
    }
}

template <int EPI>
__global__ __launch_bounds__(256)
void tgemm(const __nv_bfloat16* __restrict__ Ah, const __nv_bfloat16* __restrict__ Al,
           const __nv_bfloat16* __restrict__ Bh, const __nv_bfloat16* __restrict__ Bl,
           float* __restrict__ C, const float* __restrict__ aux,
           __nv_bfloat16* __restrict__ Oh, __nv_bfloat16* __restrict__ Ol,
           int M, int N, int K) {
    extern __shared__ __align__(16) uint8_t sm8[];
    uint32_t sb = (uint32_t)__cvta_generic_to_shared(sm8);

    int tid = threadIdx.x;
    int l   = tid & 31;
    int w   = tid >> 5;
    int wm  = w >> 2;           // 0..1
    int wn  = w & 3;            // 0..3
    int bm  = blockIdx.y * 128;
    int bn  = blockIdx.x * 128;

    float acc[4][4][4];
#pragma unroll
    for (int mi = 0; mi < 4; mi++)
#pragma unroll
        for (int ni = 0; ni < 4; ni++)
#pragma unroll
            for (int q = 0; q < 4; q++) acc[mi][ni][q] = 0.f;

    auto load_stage = [&](int s, int k0) {
        uint32_t st = sb + s * STAGE_BYTES;
#pragma unroll
        for (int q = 0; q < 2; q++) {
            int gid = tid + q * 256;
            int row = gid >> 2, kg = gid & 3;
            uint32_t off = goff(row, kg);
            size_t ga = (size_t)(bm + row) * K + k0 + kg * 8;
            size_t gb = (size_t)(bn + row) * K + k0 + kg * 8;
            cpa16(st + off,                 Ah + ga);
            cpa16(st + TILE_BYTES + off,    Al + ga);
            cpa16(st + 2*TILE_BYTES + off,  Bh + gb);
            cpa16(st + 3*TILE_BYTES + off,  Bl + gb);
        }
        asm volatile("cp.async.commit_group;\n" ::);
    };

    int nt = K / 32;
    load_stage(0, 0);
    load_stage(1, 32);
    load_stage(2, 64);

#pragma unroll 1
    for (int i = 0; i < nt; i++) {
        int rem = nt - 1 - i;
        if (rem >= 2)      asm volatile("cp.async.wait_group 2;\n" ::);
        else if (rem == 1) asm volatile("cp.async.wait_group 1;\n" ::);
        else               asm volatile("cp.async.wait_group 0;\n" ::);
        __syncthreads();

        uint32_t st = sb + (i & 3) * STAGE_BYTES;
        int sub = l >> 3;
#pragma unroll
        for (int ks = 0; ks < 2; ks++) {
            uint32_t ah[4][4], al[4][4], bh[2][4], bl[2][4];
#pragma unroll
            for (int mi = 0; mi < 4; mi++) {
                int row = wm * 64 + mi * 16 + (l & 7) + ((sub & 1) << 3);
                int kg  = ks * 2 + (sub >> 1);
                uint32_t a = st + goff(row, kg);
                ldsm4(ah[mi], a);
                ldsm4(al[mi], a + TILE_BYTES);
            }
#pragma unroll
            for (int g = 0; g < 2; g++) {
                int row = wn * 32 + g * 16 + (l & 7) + ((sub >> 1) << 3);
                int kg  = ks * 2 + (sub & 1);
                uint32_t b = st + 2*TILE_BYTES + goff(row, kg);
                ldsm4(bh[g], b);
                ldsm4(bl[g], b + TILE_BYTES);
            }
#pragma unroll
            for (int mi = 0; mi < 4; mi++)
#pragma unroll
                for (int ni = 0; ni < 4; ni++) {
                    int g = ni >> 1, o = (ni & 1) * 2;
                    mma16816(acc[mi][ni], al[mi], bh[g][o], bh[g][o + 1]);
                }
#pragma unroll
            for (int mi = 0; mi < 4; mi++)
#pragma unroll
                for (int ni = 0; ni < 4; ni++) {
                    int g = ni >> 1, o = (ni & 1) * 2;
                    mma16816(acc[mi][ni], ah[mi], bl[g][o], bl[g][o + 1]);
                }
#pragma unroll
            for (int mi = 0; mi < 4; mi++)
#pragma unroll
                for (int ni = 0; ni < 4; ni++) {
                    int g = ni >> 1, o = (ni & 1) * 2;
                    mma16816(acc[mi][ni], ah[mi], bh[g][o], bh[g][o + 1]);
                }
        }
        if (i + 3 < nt) load_stage((i + 3) & 3, (i + 3) * 32);
    }

    // ---- epilogue ----
#pragma unroll
    for (int mi = 0; mi < 4; mi++) {
#pragma unroll
        for (int ni = 0; ni < 4; ni++) {
            int r0 = bm + wm * 64 + mi * 16 + (l >> 2);
            int c0 = bn + wn * 32 + ni * 8 + (l & 3) * 2;
            size_t i0 = (size_t)r0 * N + c0;
            size_t i1 = (size_t)(r0 + 8) * N + c0;
            epi1<EPI>(C, Oh, Ol, aux, i0,     acc[mi][ni][0]);
            epi1<EPI>(C, Oh, Ol, aux, i0 + 1, acc[mi][ni][1]);
            epi1<EPI>(C, Oh, Ol, aux, i1,     acc[mi][ni][2]);
            epi1<EPI>(C, Oh, Ol, aux, i1 + 1, acc[mi][ni][3]);
        }
    }
}

// ---------------- host orchestration ---------------------------------------
extern "C" void kernel_launch(void* const* d_in, const int* in_sizes, int n_in,
                              void* d_out, int out_size) {
    (void)in_sizes; (void)n_in; (void)out_size;
    const float* x     = (const float*)d_in[0];
    const float* prew  = (const float*)d_in[1];
    const float* preb  = (const float*)d_in[2];
    const float* ln1w  = (const float*)d_in[3];
    const float* ln1b  = (const float*)d_in[4];
    const float* ln2w  = (const float*)d_in[5];
    const float* ln2b  = (const float*)d_in[6];
    const float* td    = (const float*)d_in[7];
    const float* tf    = (const float*)d_in[8];
    const float* amk   = (const float*)d_in[9];
    const float* amv   = (const float*)d_in[10];
    const float* amr   = (const float*)d_in[11];
    const float* Wk    = (const float*)d_in[12];
    const float* Wv    = (const float*)d_in[13];
    const float* Wr    = (const float*)d_in[14];
    const float* Wo    = (const float*)d_in[15];
    const float* fmk   = (const float*)d_in[16];
    const float* fmr   = (const float*)d_in[17];
    const float* Fk    = (const float*)d_in[18];
    const float* Fv    = (const float*)d_in[19];
    const float* Fr    = (const float*)d_in[20];
    const float* lnow  = (const float*)d_in[21];
    const float* lnob  = (const float*)d_in[22];
    const float* headw = (const float*)d_in[23];

    float *h, *k, *v, *r;
    __nv_bfloat16 *wh, *wl, *xkh, *xkl, *xvh, *xvl, *xrh, *xrl, *ath, *atl, *kfh, *kfl;
    cudaGetSymbolAddress((void**)&h,   g_h);
    cudaGetSymbolAddress((void**)&k,   g_k);
    cudaGetSymbolAddress((void**)&v,   g_v);
    cudaGetSymbolAddress((void**)&r,   g_r);
    cudaGetSymbolAddress((void**)&wh,  g_wh);
    cudaGetSymbolAddress((void**)&wl,  g_wl);
    cudaGetSymbolAddress((void**)&xkh, g_xkh);
    cudaGetSymbolAddress((void**)&xkl, g_xkl);
    cudaGetSymbolAddress((void**)&xvh, g_xvh);
    cudaGetSymbolAddress((void**)&xvl, g_xvl);
    cudaGetSymbolAddress((void**)&xrh, g_xrh);
    cudaGetSymbolAddress((void**)&xrl, g_xrl);
    cudaGetSymbolAddress((void**)&ath, g_ath);
    cudaGetSymbolAddress((void**)&atl, g_atl);
    cudaGetSymbolAddress((void**)&kfh, g_kfh);
    cudaGetSymbolAddress((void**)&kfl, g_kfl);

    cudaFuncSetAttribute(tgemm<0>, cudaFuncAttributeMaxDynamicSharedMemorySize, GEMM_SMEM);
    cudaFuncSetAttribute(tgemm<1>, cudaFuncAttributeMaxDynamicSharedMemorySize, GEMM_SMEM);
    cudaFuncSetAttribute(tgemm<2>, cudaFuncAttributeMaxDynamicSharedMemorySize, GEMM_SMEM);
    cudaFuncSetAttribute(tgemm<3>, cudaFuncAttributeMaxDynamicSharedMemorySize, GEMM_SMEM);
    cudaFuncSetAttribute(tgemm<4>, cudaFuncAttributeMaxDynamicSharedMemorySize, GEMM_SMEM);

    dim3 blk(256);
    dim3 tb(32, 8);
    dim3 gHH(H_ / 32, H_ / 32);     // transT grids
    dim3 gHF(FF_ / 32, H_ / 32);    // Fk: K=H, N=FF
    dim3 gFH(H_ / 32, FF_ / 32);    // Fv: K=FF, N=H
    dim3 gH(H_ / 128,  BT_ / 128);  // GEMM grids
    dim3 gF(FF_ / 128, BT_ / 128);

    // ---- weight transpose + split (independent of activations) ----
    for (int i = 0; i < L_; i++) {
        size_t wb = (size_t)i * WL_;
        transT<<<gHH, tb>>>(Wk + (size_t)i * H2_,  wh + wb + OWK_, wl + wb + OWK_, H_, H_);
        transT<<<gHH, tb>>>(Wv + (size_t)i * H2_,  wh + wb + OWV_, wl + wb + OWV_, H_, H_);
        transT<<<gHH, tb>>>(Wr + (size_t)i * H2_,  wh + wb + OWR_, wl + wb + OWR_, H_, H_);
        transT<<<gHH, tb>>>(Wo + (size_t)i * H2_,  wh + wb + OWO_, wl + wb + OWO_, H_, H_);
        transT<<<gHH, tb>>>(Fr + (size_t)i * H2_,  wh + wb + OFR_, wl + wb + OFR_, H_, H_);
        transT<<<gHF, tb>>>(Fk + (size_t)i * HFF_, wh + wb + OFK_, wl + wb + OFK_, H_, FF_);
        transT<<<gFH, tb>>>(Fv + (size_t)i * HFF_, wh + wb + OFV_, wl + wb + OFV_, FF_, H_);
    }
    size_t hb = (size_t)L_ * WL_;
    transT<<<gHH, tb>>>(headw, wh + hb, wl + hb, H_, H_);

    // ---- block 0 pre-LN ----
    ln_kernel<<<BT_, blk>>>(x, prew, preb, h);

    for (int i = 0; i < L_; i++) {
        size_t oH = (size_t)i * H_;
        size_t wb = (size_t)i * WL_;

        // --- time mixing ---
        prep_mix<<<BT_, blk>>>(h, ln1w + oH, ln1b + oH, amk + oH, amv + oH, amr + oH,
                               xkh, xkl, xvh, xvl, xrh, xrl);
        tgemm<0><<<gH, blk, GEMM_SMEM>>>(xkh, xkl, wh + wb + OWK_, wl + wb + OWK_,
                                         k, nullptr, nullptr, nullptr, BT_, H_, H_);
        tgemm<0><<<gH, blk, GEMM_SMEM>>>(xvh, xvl, wh + wb + OWV_, wl + wb + OWV_,
                                         v, nullptr, nullptr, nullptr, BT_, H_, H_);
        tgemm<1><<<gH, blk, GEMM_SMEM>>>(xrh, xrl, wh + wb + OWR_, wl + wb + OWR_,
                                         r, nullptr, nullptr, nullptr, BT_, H_, H_);
        wkv_kernel<<<(B_ * H_ + 255) / 256, blk>>>(k, v, r, td + oH, tf + oH, ath, atl);
        tgemm<2><<<gH, blk, GEMM_SMEM>>>(ath, atl, wh + wb + OWO_, wl + wb + OWO_,
                                         h, nullptr, nullptr, nullptr, BT_, H_, H_);

        // --- channel mixing ---
        prep_mix<<<BT_, blk>>>(h, ln2w + oH, ln2b + oH, fmk + oH, nullptr, fmr + oH,
                               xkh, xkl, nullptr, nullptr, xrh, xrl);
        tgemm<4><<<gF, blk, GEMM_SMEM>>>(xkh, xkl, wh + wb + OFK_, wl + wb + OFK_,
                                         nullptr, nullptr, kfh, kfl, BT_, FF_, H_);
        tgemm<1><<<gH, blk, GEMM_SMEM>>>(xrh, xrl, wh + wb + OFR_, wl + wb + OFR_,
                                         r, nullptr, nullptr, nullptr, BT_, H_, H_);
        tgemm<3><<<gH, blk, GEMM_SMEM>>>(kfh, kfl, wh + wb + OFV_, wl + wb + OFV_,
                                         h, r, nullptr, nullptr, BT_, H_, FF_);
    }

    ln_split<<<BT_, blk>>>(h, lnow, lnob, xkh, xkl);
    tgemm<0><<<gH, blk, GEMM_SMEM>>>(xkh, xkl, wh + hb, wl + hb,
                                     (float*)d_out, nullptr, nullptr, nullptr, BT_, H_, H_);
}